// round 14
// baseline (speedup 1.0000x reference)
#include <cuda_runtime.h>

#define T_STEPS 512
#define BATCH   4096
#define DIN     4
#define HID     32
#define NB      8              // batch elements per producer/consumer warp pair
#define BP      (NB / 2)       // batch-pairs
#define PAIRS   4              // pairs per block; producer wid=p (SMSP p), consumer wid=4+p (SMSP p)
#define THREADS (PAIRS * 64)             // 256
#define NBLOCKS (BATCH / (PAIRS * NB))   // 128
#define WHH0_REG 8             // producer: whh0 k-slices cached in registers
#define W1P_REG  16            // producer: wih1 k-slices (k<16) cached in registers

typedef unsigned long long u64;

struct __align__(16) Smem {
    // packed gate weights: [k][u] = (Wi[u,k], Wf[u,k], Wg[u,k], Wo[u,k])
    float4 whh0[HID][HID];   // 16 KB
    float4 wih1[HID][HID];   // 16 KB
    float4 whh1[HID][HID];   // 16 KB
    float4 wih0[DIN][HID];   //  2 KB
    float4 bias0[HID];
    float4 bias1[HID];
    // h1 handoff: per-pair double-buffered, natural batch-pairs
    u64 h1buf[PAIRS][2][HID][BP];   // 8 KB
    // layer-2 partial gate accumulators: bias1 + sum_{k<16} Wih1[k] h1[k]
    // [pair][buf][j][lane], j = gate*2 + bp/2, each entry = (acc[2j], acc[2j+1])
    ulonglong2 part[PAIRS][2][8][32];  // 32 KB
    // h2 state (consumer-warp private), natural pairs
    u64 h2s[PAIRS][HID][BP];        // 4 KB
    float wout[HID];
    float bout;
};

__device__ __forceinline__ u64 pk2(float lo, float hi) {
    u64 r; asm("mov.b64 %0,{%1,%2};" : "=l"(r) : "f"(lo), "f"(hi)); return r;
}
__device__ __forceinline__ void upk2(u64 v, float& lo, float& hi) {
    asm("mov.b64 {%0,%1},%2;" : "=f"(lo), "=f"(hi) : "l"(v));
}
__device__ __forceinline__ u64 ffma2(u64 a, u64 b, u64 c) {
    u64 d; asm("fma.rn.f32x2 %0,%1,%2,%3;" : "=l"(d) : "l"(a), "l"(b), "l"(c)); return d;
}
__device__ __forceinline__ float tanh_ap(float x) {
    float y; asm("tanh.approx.f32 %0,%1;" : "=f"(y) : "f"(x)); return y;
}
__device__ __forceinline__ float sigf(float x) { return fmaf(tanh_ap(0.5f * x), 0.5f, 0.5f); }

__device__ __forceinline__ void bar_sync64(int id) {
    asm volatile("bar.sync %0, 64;" :: "r"(id) : "memory");
}
__device__ __forceinline__ void bar_arrive64(int id) {
    asm volatile("bar.arrive %0, 64;" :: "r"(id) : "memory");
}

// k-slice of the gate GEMM from two u64 weight pairs: (wi,wf),(wg,wo)
#define GATE_K4R(WX, WY, HV)                                                  \
    do {                                                                      \
        float wi_, wf_, wg_, wo_;                                             \
        upk2((WX), wi_, wf_); upk2((WY), wg_, wo_);                           \
        u64 wii_ = pk2(wi_, wi_), wff_ = pk2(wf_, wf_);                       \
        u64 wgg_ = pk2(wg_, wg_), woo_ = pk2(wo_, wo_);                       \
        _Pragma("unroll")                                                     \
        for (int bp = 0; bp < BP; ++bp) {                                     \
            ai[bp] = ffma2(wii_, (HV)[bp], ai[bp]);                           \
            af[bp] = ffma2(wff_, (HV)[bp], af[bp]);                           \
            ag[bp] = ffma2(wgg_, (HV)[bp], ag[bp]);                           \
            ao[bp] = ffma2(woo_, (HV)[bp], ao[bp]);                           \
        }                                                                     \
    } while (0)

__global__ void __launch_bounds__(THREADS, 1) lstm2_kernel(
    const float* __restrict__ x,
    const float* __restrict__ Wih0, const float* __restrict__ Whh0,
    const float* __restrict__ bih0, const float* __restrict__ bhh0,
    const float* __restrict__ Wih1, const float* __restrict__ Whh1,
    const float* __restrict__ bih1, const float* __restrict__ bhh1,
    const float* __restrict__ Wout, const float* __restrict__ boutp,
    float* __restrict__ out)
{
    extern __shared__ unsigned char smem_raw[];
    Smem* s = reinterpret_cast<Smem*>(smem_raw);

    const int tid  = threadIdx.x;
    const int w    = tid >> 5;
    const int lane = tid & 31;
    const int role = w >> 2;     // 0 = producer (warps 0-3), 1 = consumer (warps 4-7)
    const int pair = w & 3;      // SMSP index; producer & consumer of a pair share an SMSP

    // ---- stage packed weights into shared ----
    for (int i = tid; i < HID * HID; i += THREADS) {
        int k = i >> 5, u = i & 31;
        s->whh0[k][u] = make_float4(Whh0[u * HID + k],        Whh0[(32 + u) * HID + k],
                                    Whh0[(64 + u) * HID + k], Whh0[(96 + u) * HID + k]);
        s->wih1[k][u] = make_float4(Wih1[u * HID + k],        Wih1[(32 + u) * HID + k],
                                    Wih1[(64 + u) * HID + k], Wih1[(96 + u) * HID + k]);
        s->whh1[k][u] = make_float4(Whh1[u * HID + k],        Whh1[(32 + u) * HID + k],
                                    Whh1[(64 + u) * HID + k], Whh1[(96 + u) * HID + k]);
    }
    for (int i = tid; i < DIN * HID; i += THREADS) {
        int k = i >> 5, u = i & 31;
        s->wih0[k][u] = make_float4(Wih0[u * DIN + k],        Wih0[(32 + u) * DIN + k],
                                    Wih0[(64 + u) * DIN + k], Wih0[(96 + u) * DIN + k]);
    }
    if (tid < HID) {
        int u = tid;
        s->bias0[u] = make_float4(bih0[u] + bhh0[u],           bih0[32 + u] + bhh0[32 + u],
                                  bih0[64 + u] + bhh0[64 + u], bih0[96 + u] + bhh0[96 + u]);
        s->bias1[u] = make_float4(bih1[u] + bhh1[u],           bih1[32 + u] + bhh1[32 + u],
                                  bih1[64 + u] + bhh1[64 + u], bih1[96 + u] + bhh1[96 + u]);
        s->wout[u] = Wout[u];
        if (u == 0) s->bout = boutp[0];
    }
    {
        u64* z = &s->h1buf[0][0][0][0];
        for (int i = tid; i < PAIRS * 2 * HID * BP; i += THREADS) z[i] = 0ull;
        u64* z2 = &s->h2s[0][0][0];
        for (int i = tid; i < PAIRS * HID * BP; i += THREADS) z2[i] = 0ull;
    }
    __syncthreads();

    const int batch0 = (blockIdx.x * PAIRS + pair) * NB;
    const int bf0 = pair * 4 + 0, bf1 = pair * 4 + 1;
    const int be0 = pair * 4 + 2, be1 = pair * 4 + 3;

    u64 ai[BP], af[BP], ag[BP], ao[BP];

    if (role == 0) {
        // ================= producer: layer 1 + first half of layer-2 input GEMM =================
        const float* xbase = x + (size_t)batch0 * T_STEPS * DIN;

        float c1[NB];
        #pragma unroll
        for (int b = 0; b < NB; ++b) c1[b] = 0.0f;

        const float4 b0v = s->bias0[lane];
        const u64 bI = pk2(b0v.x, b0v.x), bF = pk2(b0v.y, b0v.y);
        const u64 bG = pk2(b0v.z, b0v.z), bO = pk2(b0v.w, b0v.w);
        const float4 b1v = s->bias1[lane];
        const u64 b1I = pk2(b1v.x, b1v.x), b1F = pk2(b1v.y, b1v.y);
        const u64 b1G = pk2(b1v.z, b1v.z), b1O = pk2(b1v.w, b1v.w);

        // register caches
        u64 w0x[DIN][2];
        #pragma unroll
        for (int k = 0; k < DIN; ++k) {
            ulonglong2 wp = *reinterpret_cast<const ulonglong2*>(&s->wih0[k][lane]);
            w0x[k][0] = wp.x; w0x[k][1] = wp.y;
        }
        u64 wr0[WHH0_REG][2];
        #pragma unroll
        for (int k = 0; k < WHH0_REG; ++k) {
            ulonglong2 wp = *reinterpret_cast<const ulonglong2*>(&s->whh0[k][lane]);
            wr0[k][0] = wp.x; wr0[k][1] = wp.y;
        }
        u64 w1p[W1P_REG][2];   // wih1 slices k<16 (for the partial layer-2 GEMM)
        #pragma unroll
        for (int k = 0; k < W1P_REG; ++k) {
            ulonglong2 wp = *reinterpret_cast<const ulonglong2*>(&s->wih1[k][lane]);
            w1p[k][0] = wp.x; w1p[k][1] = wp.y;
        }

        float4 xf[NB];
        #pragma unroll
        for (int b = 0; b < NB; ++b)
            xf[b] = *reinterpret_cast<const float4*>(xbase + (size_t)b * T_STEPS * DIN);

        for (int t = 0; t < T_STEPS; ++t) {
            const int buf = t & 1;
            if (t >= 2) bar_sync64(buf ? be1 : be0);   // consumer done with this buffer

            #pragma unroll
            for (int bp = 0; bp < BP; ++bp) { ai[bp] = bI; af[bp] = bF; ag[bp] = bG; ao[bp] = bO; }

            // x contribution from register weights
            {
                u64 hv[BP];
                #pragma unroll
                for (int bp = 0; bp < BP; ++bp) hv[bp] = pk2(xf[2*bp].x, xf[2*bp+1].x);
                GATE_K4R(w0x[0][0], w0x[0][1], hv);
                #pragma unroll
                for (int bp = 0; bp < BP; ++bp) hv[bp] = pk2(xf[2*bp].y, xf[2*bp+1].y);
                GATE_K4R(w0x[1][0], w0x[1][1], hv);
                #pragma unroll
                for (int bp = 0; bp < BP; ++bp) hv[bp] = pk2(xf[2*bp].z, xf[2*bp+1].z);
                GATE_K4R(w0x[2][0], w0x[2][1], hv);
                #pragma unroll
                for (int bp = 0; bp < BP; ++bp) hv[bp] = pk2(xf[2*bp].w, xf[2*bp+1].w);
                GATE_K4R(w0x[3][0], w0x[3][1], hv);
            }
            if (t + 1 < T_STEPS) {
                const float* xt = xbase + (size_t)(t + 1) * DIN;
                #pragma unroll
                for (int b = 0; b < NB; ++b)
                    xf[b] = *reinterpret_cast<const float4*>(xt + (size_t)b * T_STEPS * DIN);
            }

            // recurrent: h1(t-1) from other buffer
            {
                const u64* hp = &s->h1buf[pair][buf ^ 1][0][0];
                #pragma unroll
                for (int k = 0; k < WHH0_REG; ++k) {
                    const ulonglong2 hA = *reinterpret_cast<const ulonglong2*>(hp + k * BP);
                    const ulonglong2 hB = *reinterpret_cast<const ulonglong2*>(hp + k * BP + 2);
                    u64 hv[BP] = { hA.x, hA.y, hB.x, hB.y };
                    GATE_K4R(wr0[k][0], wr0[k][1], hv);
                }
                #pragma unroll
                for (int k = WHH0_REG; k < HID; ++k) {
                    const ulonglong2 wp = *reinterpret_cast<const ulonglong2*>(&s->whh0[k][lane]);
                    const ulonglong2 hA = *reinterpret_cast<const ulonglong2*>(hp + k * BP);
                    const ulonglong2 hB = *reinterpret_cast<const ulonglong2*>(hp + k * BP + 2);
                    u64 hv[BP] = { hA.x, hA.y, hB.x, hB.y };
                    GATE_K4R(wp.x, wp.y, hv);
                }
            }

            // activations + h1 store
            #pragma unroll
            for (int bp = 0; bp < BP; ++bp) {
                float i0, i1, f0, f1, g0, g1, o0, o1;
                upk2(ai[bp], i0, i1); upk2(af[bp], f0, f1);
                upk2(ag[bp], g0, g1); upk2(ao[bp], o0, o1);
                float ca = sigf(f0) * c1[2*bp]   + sigf(i0) * tanh_ap(g0);
                float cb = sigf(f1) * c1[2*bp+1] + sigf(i1) * tanh_ap(g1);
                c1[2*bp]   = ca;  c1[2*bp+1] = cb;
                float ha = sigf(o0) * tanh_ap(ca);
                float hb = sigf(o1) * tanh_ap(cb);
                s->h1buf[pair][buf][lane][bp] = pk2(ha, hb);
            }
            __syncwarp();   // h1(t) fully written by this warp; safe to read back

            // ---- partial layer-2 input GEMM: bias1 + sum_{k<16} Wih1[k]·h1(t)[k] ----
            #pragma unroll
            for (int bp = 0; bp < BP; ++bp) { ai[bp] = b1I; af[bp] = b1F; ag[bp] = b1G; ao[bp] = b1O; }
            {
                const u64* hp = &s->h1buf[pair][buf][0][0];
                #pragma unroll
                for (int k = 0; k < W1P_REG; ++k) {
                    const ulonglong2 hA = *reinterpret_cast<const ulonglong2*>(hp + k * BP);
                    const ulonglong2 hB = *reinterpret_cast<const ulonglong2*>(hp + k * BP + 2);
                    u64 hv[BP] = { hA.x, hA.y, hB.x, hB.y };
                    GATE_K4R(w1p[k][0], w1p[k][1], hv);
                }
            }
            {
                ulonglong2* pp = &s->part[pair][buf][0][lane];
                pp[0 * 32] = make_ulonglong2(ai[0], ai[1]);
                pp[1 * 32] = make_ulonglong2(ai[2], ai[3]);
                pp[2 * 32] = make_ulonglong2(af[0], af[1]);
                pp[3 * 32] = make_ulonglong2(af[2], af[3]);
                pp[4 * 32] = make_ulonglong2(ag[0], ag[1]);
                pp[5 * 32] = make_ulonglong2(ag[2], ag[3]);
                pp[6 * 32] = make_ulonglong2(ao[0], ao[1]);
                pp[7 * 32] = make_ulonglong2(ao[2], ao[3]);
            }
            __threadfence_block();    // h1 + partial visible to consumer warp
            bar_arrive64(buf ? bf1 : bf0);   // h1(t)+partial published
        }
    } else {
        // ================= consumer: rest of layer 2 =================
        float c2[NB], h2v[NB];
        #pragma unroll
        for (int b = 0; b < NB; ++b) { c2[b] = 0.0f; h2v[b] = 0.0f; }

        // register-cache ALL whh1 slices (64 u64 = 128 regs)
        u64 wr1[HID][2];
        #pragma unroll
        for (int k = 0; k < HID; ++k) {
            ulonglong2 wp = *reinterpret_cast<const ulonglong2*>(&s->whh1[k][lane]);
            wr1[k][0] = wp.x; wr1[k][1] = wp.y;
        }

        for (int t = 0; t < T_STEPS; ++t) {
            const int buf = t & 1;
            bar_sync64(buf ? bf1 : bf0);     // h1(t) + partial ready

            // init accumulators from producer's partial (bias1 + k<16 already done)
            {
                const ulonglong2* pp = &s->part[pair][buf][0][lane];
                ulonglong2 q0 = pp[0 * 32], q1 = pp[1 * 32];
                ulonglong2 q2 = pp[2 * 32], q3 = pp[3 * 32];
                ulonglong2 q4 = pp[4 * 32], q5 = pp[5 * 32];
                ulonglong2 q6 = pp[6 * 32], q7 = pp[7 * 32];
                ai[0] = q0.x; ai[1] = q0.y; ai[2] = q1.x; ai[3] = q1.y;
                af[0] = q2.x; af[1] = q2.y; af[2] = q3.x; af[3] = q3.y;
                ag[0] = q4.x; ag[1] = q4.y; ag[2] = q5.x; ag[3] = q5.y;
                ao[0] = q6.x; ao[1] = q6.y; ao[2] = q7.x; ao[3] = q7.y;
            }

            // remaining input contribution: Wih1 k=16..31 (smem weights + h1 LDS)
            {
                const u64* hp = &s->h1buf[pair][buf][0][0];
                #pragma unroll
                for (int k = W1P_REG; k < HID; ++k) {
                    const ulonglong2 wp = *reinterpret_cast<const ulonglong2*>(&s->wih1[k][lane]);
                    const ulonglong2 hA = *reinterpret_cast<const ulonglong2*>(hp + k * BP);
                    const ulonglong2 hB = *reinterpret_cast<const ulonglong2*>(hp + k * BP + 2);
                    u64 hv[BP] = { hA.x, hA.y, hB.x, hB.y };
                    GATE_K4R(wp.x, wp.y, hv);
                }
            }
            bar_arrive64(buf ? be1 : be0);   // h1 buffer + partial consumed

            // recurrent contribution: Whh1 . h2(t-1)  (register weights)
            {
                const u64* hp = &s->h2s[pair][0][0];
                #pragma unroll
                for (int k = 0; k < HID; ++k) {
                    const ulonglong2 hA = *reinterpret_cast<const ulonglong2*>(hp + k * BP);
                    const ulonglong2 hB = *reinterpret_cast<const ulonglong2*>(hp + k * BP + 2);
                    u64 hv[BP] = { hA.x, hA.y, hB.x, hB.y };
                    GATE_K4R(wr1[k][0], wr1[k][1], hv);
                }
            }

            // activations + h2 store (bias already in partial)
            __syncwarp();   // all lanes done reading old h2s
            #pragma unroll
            for (int bp = 0; bp < BP; ++bp) {
                float i0, i1, f0, f1, g0, g1, o0, o1;
                upk2(ai[bp], i0, i1); upk2(af[bp], f0, f1);
                upk2(ag[bp], g0, g1); upk2(ao[bp], o0, o1);
                float ca = sigf(f0) * c2[2*bp]   + sigf(i0) * tanh_ap(g0);
                float cb = sigf(f1) * c2[2*bp+1] + sigf(i1) * tanh_ap(g1);
                c2[2*bp]   = ca;  c2[2*bp+1] = cb;
                h2v[2*bp]   = sigf(o0) * tanh_ap(ca);
                h2v[2*bp+1] = sigf(o1) * tanh_ap(cb);
                s->h2s[pair][lane][bp] = pk2(h2v[2*bp], h2v[2*bp+1]);
            }
            __syncwarp();   // new h2 visible to whole warp
        }

        // ---- output head ----
        const float wo = s->wout[lane];
        #pragma unroll
        for (int b = 0; b < NB; ++b) {
            float v = h2v[b] * wo;
            #pragma unroll
            for (int off = 16; off; off >>= 1) v += __shfl_xor_sync(0xffffffffu, v, off);
            if (lane == 0) out[batch0 + b] = v + s->bout;
        }
    }
}

extern "C" void kernel_launch(void* const* d_in, const int* in_sizes, int n_in,
                              void* d_out, int out_size)
{
    (void)in_sizes; (void)n_in; (void)out_size;
    const size_t smem = sizeof(Smem);
    cudaFuncSetAttribute(lstm2_kernel, cudaFuncAttributeMaxDynamicSharedMemorySize, (int)smem);
    lstm2_kernel<<<NBLOCKS, THREADS, smem>>>(
        (const float*)d_in[0],
        (const float*)d_in[1], (const float*)d_in[2],
        (const float*)d_in[3], (const float*)d_in[4],
        (const float*)d_in[5], (const float*)d_in[6],
        (const float*)d_in[7], (const float*)d_in[8],
        (const float*)d_in[9], (const float*)d_in[10],
        (float*)d_out);
}

// round 15
// speedup vs baseline: 1.1110x; 1.1110x over previous
#include <cuda_runtime.h>

#define T_STEPS 512
#define BATCH   4096
#define DIN     4
#define HID     32
#define NB      8              // batch elements per producer/consumer warp pair
#define BP      (NB / 2)       // batch-pairs
#define PAIRS   4              // pairs per block; producer wid=p (SMSP p), consumer wid=4+p (SMSP p)
#define THREADS (PAIRS * 64)             // 256
#define NBLOCKS (BATCH / (PAIRS * NB))   // 128
#define WHH0_REG 32            // producer: ALL whh0 k-slices cached in registers

typedef unsigned long long u64;

struct __align__(16) Smem {
    // packed gate weights: [k][u] = (Wi[u,k]*.5, Wf[u,k]*.5, Wg[u,k], Wo[u,k]*.5)
    // i/f/o rows pre-scaled by 0.5 so sigmoid needs no input multiply.
    float4 whh0[HID][HID];   // 16 KB
    float4 wih1[HID][HID];   // 16 KB
    float4 whh1[HID][HID];   // 16 KB
    float4 wih0[DIN][HID];   //  2 KB
    float4 bias0[HID];
    float4 bias1[HID];
    // h1 handoff: per-pair double-buffered, natural batch-pairs
    u64 h1buf[PAIRS][2][HID][BP];   // 8 KB
    // h2 state (consumer-warp private), natural pairs
    u64 h2s[PAIRS][HID][BP];        // 4 KB
    float wout[HID];
    float bout;
};

__device__ __forceinline__ u64 pk2(float lo, float hi) {
    u64 r; asm("mov.b64 %0,{%1,%2};" : "=l"(r) : "f"(lo), "f"(hi)); return r;
}
__device__ __forceinline__ void upk2(u64 v, float& lo, float& hi) {
    asm("mov.b64 {%0,%1},%2;" : "=f"(lo), "=f"(hi) : "l"(v));
}
__device__ __forceinline__ u64 ffma2(u64 a, u64 b, u64 c) {
    u64 d; asm("fma.rn.f32x2 %0,%1,%2,%3;" : "=l"(d) : "l"(a), "l"(b), "l"(c)); return d;
}
__device__ __forceinline__ float tanh_ap(float x) {
    float y; asm("tanh.approx.f32 %0,%1;" : "=f"(y) : "f"(x)); return y;
}
// input already pre-scaled by 0.5 via the weights: sigma(2x') where x' = 0.5*pre
__device__ __forceinline__ float sig_pre(float x) { return fmaf(tanh_ap(x), 0.5f, 0.5f); }

__device__ __forceinline__ void bar_sync64(int id) {
    asm volatile("bar.sync %0, 64;" :: "r"(id) : "memory");
}
__device__ __forceinline__ void bar_arrive64(int id) {
    asm volatile("bar.arrive %0, 64;" :: "r"(id) : "memory");
}

// k-slice of the gate GEMM from two u64 weight pairs: (wi,wf),(wg,wo)
#define GATE_K4R(WX, WY, HV)                                                  \
    do {                                                                      \
        float wi_, wf_, wg_, wo_;                                             \
        upk2((WX), wi_, wf_); upk2((WY), wg_, wo_);                           \
        u64 wii_ = pk2(wi_, wi_), wff_ = pk2(wf_, wf_);                       \
        u64 wgg_ = pk2(wg_, wg_), woo_ = pk2(wo_, wo_);                       \
        _Pragma("unroll")                                                     \
        for (int bp = 0; bp < BP; ++bp) {                                     \
            ai[bp] = ffma2(wii_, (HV)[bp], ai[bp]);                           \
            af[bp] = ffma2(wff_, (HV)[bp], af[bp]);                           \
            ag[bp] = ffma2(wgg_, (HV)[bp], ag[bp]);                           \
            ao[bp] = ffma2(woo_, (HV)[bp], ao[bp]);                           \
        }                                                                     \
    } while (0)

__global__ void __launch_bounds__(THREADS, 1) lstm2_kernel(
    const float* __restrict__ x,
    const float* __restrict__ Wih0, const float* __restrict__ Whh0,
    const float* __restrict__ bih0, const float* __restrict__ bhh0,
    const float* __restrict__ Wih1, const float* __restrict__ Whh1,
    const float* __restrict__ bih1, const float* __restrict__ bhh1,
    const float* __restrict__ Wout, const float* __restrict__ boutp,
    float* __restrict__ out)
{
    extern __shared__ unsigned char smem_raw[];
    Smem* s = reinterpret_cast<Smem*>(smem_raw);

    const int tid  = threadIdx.x;
    const int w    = tid >> 5;
    const int lane = tid & 31;
    const int role = w >> 2;     // 0 = producer (warps 0-3), 1 = consumer (warps 4-7)
    const int pair = w & 3;      // SMSP index; producer & consumer of a pair share an SMSP

    // ---- stage packed weights into shared (i/f/o rows pre-scaled by 0.5) ----
    for (int i = tid; i < HID * HID; i += THREADS) {
        int k = i >> 5, u = i & 31;
        s->whh0[k][u] = make_float4(0.5f * Whh0[u * HID + k],        0.5f * Whh0[(32 + u) * HID + k],
                                    Whh0[(64 + u) * HID + k],        0.5f * Whh0[(96 + u) * HID + k]);
        s->wih1[k][u] = make_float4(0.5f * Wih1[u * HID + k],        0.5f * Wih1[(32 + u) * HID + k],
                                    Wih1[(64 + u) * HID + k],        0.5f * Wih1[(96 + u) * HID + k]);
        s->whh1[k][u] = make_float4(0.5f * Whh1[u * HID + k],        0.5f * Whh1[(32 + u) * HID + k],
                                    Whh1[(64 + u) * HID + k],        0.5f * Whh1[(96 + u) * HID + k]);
    }
    for (int i = tid; i < DIN * HID; i += THREADS) {
        int k = i >> 5, u = i & 31;
        s->wih0[k][u] = make_float4(0.5f * Wih0[u * DIN + k],        0.5f * Wih0[(32 + u) * DIN + k],
                                    Wih0[(64 + u) * DIN + k],        0.5f * Wih0[(96 + u) * DIN + k]);
    }
    if (tid < HID) {
        int u = tid;
        s->bias0[u] = make_float4(0.5f * (bih0[u] + bhh0[u]),           0.5f * (bih0[32 + u] + bhh0[32 + u]),
                                  bih0[64 + u] + bhh0[64 + u],          0.5f * (bih0[96 + u] + bhh0[96 + u]));
        s->bias1[u] = make_float4(0.5f * (bih1[u] + bhh1[u]),           0.5f * (bih1[32 + u] + bhh1[32 + u]),
                                  bih1[64 + u] + bhh1[64 + u],          0.5f * (bih1[96 + u] + bhh1[96 + u]));
        s->wout[u] = Wout[u];
        if (u == 0) s->bout = boutp[0];
    }
    {
        u64* z = &s->h1buf[0][0][0][0];
        for (int i = tid; i < PAIRS * 2 * HID * BP; i += THREADS) z[i] = 0ull;
        u64* z2 = &s->h2s[0][0][0];
        for (int i = tid; i < PAIRS * HID * BP; i += THREADS) z2[i] = 0ull;
    }
    __syncthreads();

    const int batch0 = (blockIdx.x * PAIRS + pair) * NB;
    const int bf0 = pair * 4 + 0, bf1 = pair * 4 + 1;
    const int be0 = pair * 4 + 2, be1 = pair * 4 + 3;

    u64 ai[BP], af[BP], ag[BP], ao[BP];

    if (role == 0) {
        // ================= producer: layer 1 (fully register-weighted) =================
        const float* xbase = x + (size_t)batch0 * T_STEPS * DIN;

        float c1[NB];
        #pragma unroll
        for (int b = 0; b < NB; ++b) c1[b] = 0.0f;

        const float4 b0v = s->bias0[lane];
        const u64 bI = pk2(b0v.x, b0v.x), bF = pk2(b0v.y, b0v.y);
        const u64 bG = pk2(b0v.z, b0v.z), bO = pk2(b0v.w, b0v.w);

        // register-cache: ALL weights for layer 1
        u64 w0x[DIN][2];
        #pragma unroll
        for (int k = 0; k < DIN; ++k) {
            ulonglong2 wp = *reinterpret_cast<const ulonglong2*>(&s->wih0[k][lane]);
            w0x[k][0] = wp.x; w0x[k][1] = wp.y;
        }
        u64 wr0[WHH0_REG][2];
        #pragma unroll
        for (int k = 0; k < WHH0_REG; ++k) {
            ulonglong2 wp = *reinterpret_cast<const ulonglong2*>(&s->whh0[k][lane]);
            wr0[k][0] = wp.x; wr0[k][1] = wp.y;
        }

        float4 xf[NB];
        #pragma unroll
        for (int b = 0; b < NB; ++b)
            xf[b] = *reinterpret_cast<const float4*>(xbase + (size_t)b * T_STEPS * DIN);

        for (int t = 0; t < T_STEPS; ++t) {
            const int buf = t & 1;
            if (t >= 2) bar_sync64(buf ? be1 : be0);   // consumer done with this buffer

            #pragma unroll
            for (int bp = 0; bp < BP; ++bp) { ai[bp] = bI; af[bp] = bF; ag[bp] = bG; ao[bp] = bO; }

            // x contribution from register weights
            {
                u64 hv[BP];
                #pragma unroll
                for (int bp = 0; bp < BP; ++bp) hv[bp] = pk2(xf[2*bp].x, xf[2*bp+1].x);
                GATE_K4R(w0x[0][0], w0x[0][1], hv);
                #pragma unroll
                for (int bp = 0; bp < BP; ++bp) hv[bp] = pk2(xf[2*bp].y, xf[2*bp+1].y);
                GATE_K4R(w0x[1][0], w0x[1][1], hv);
                #pragma unroll
                for (int bp = 0; bp < BP; ++bp) hv[bp] = pk2(xf[2*bp].z, xf[2*bp+1].z);
                GATE_K4R(w0x[2][0], w0x[2][1], hv);
                #pragma unroll
                for (int bp = 0; bp < BP; ++bp) hv[bp] = pk2(xf[2*bp].w, xf[2*bp+1].w);
                GATE_K4R(w0x[3][0], w0x[3][1], hv);
            }
            if (t + 1 < T_STEPS) {
                const float* xt = xbase + (size_t)(t + 1) * DIN;
                #pragma unroll
                for (int b = 0; b < NB; ++b)
                    xf[b] = *reinterpret_cast<const float4*>(xt + (size_t)b * T_STEPS * DIN);
            }

            // recurrent: h1(t-1) from other buffer, ALL weights in registers —
            // producer is FFMA2-eligible except for the short h1-LDS stream,
            // so it covers the FMA pipe whenever the consumer stalls.
            {
                const u64* hp = &s->h1buf[pair][buf ^ 1][0][0];
                #pragma unroll
                for (int k = 0; k < WHH0_REG; ++k) {
                    const ulonglong2 hA = *reinterpret_cast<const ulonglong2*>(hp + k * BP);
                    const ulonglong2 hB = *reinterpret_cast<const ulonglong2*>(hp + k * BP + 2);
                    u64 hv[BP] = { hA.x, hA.y, hB.x, hB.y };
                    GATE_K4R(wr0[k][0], wr0[k][1], hv);
                }
            }

            // activations + h1 store (i/f/o pre-scaled: sig_pre has no input mul)
            #pragma unroll
            for (int bp = 0; bp < BP; ++bp) {
                float i0, i1, f0, f1, g0, g1, o0, o1;
                upk2(ai[bp], i0, i1); upk2(af[bp], f0, f1);
                upk2(ag[bp], g0, g1); upk2(ao[bp], o0, o1);
                float ca = sig_pre(f0) * c1[2*bp]   + sig_pre(i0) * tanh_ap(g0);
                float cb = sig_pre(f1) * c1[2*bp+1] + sig_pre(i1) * tanh_ap(g1);
                c1[2*bp]   = ca;  c1[2*bp+1] = cb;
                float ha = sig_pre(o0) * tanh_ap(ca);
                float hb = sig_pre(o1) * tanh_ap(cb);
                s->h1buf[pair][buf][lane][bp] = pk2(ha, hb);
            }
            __syncwarp();
            __threadfence_block();
            bar_arrive64(buf ? bf1 : bf0);   // h1(t) published
        }
    } else {
        // ================= consumer: layer 2 =================
        float c2[NB], h2v[NB];
        #pragma unroll
        for (int b = 0; b < NB; ++b) { c2[b] = 0.0f; h2v[b] = 0.0f; }

        const float4 b1v = s->bias1[lane];
        const u64 bI = pk2(b1v.x, b1v.x), bF = pk2(b1v.y, b1v.y);
        const u64 bG = pk2(b1v.z, b1v.z), bO = pk2(b1v.w, b1v.w);

        // register-cache ALL whh1 slices (64 u64 = 128 regs)
        u64 wr1[HID][2];
        #pragma unroll
        for (int k = 0; k < HID; ++k) {
            ulonglong2 wp = *reinterpret_cast<const ulonglong2*>(&s->whh1[k][lane]);
            wr1[k][0] = wp.x; wr1[k][1] = wp.y;
        }

        for (int t = 0; t < T_STEPS; ++t) {
            const int buf = t & 1;
            bar_sync64(buf ? bf1 : bf0);     // h1(t) ready

            #pragma unroll
            for (int bp = 0; bp < BP; ++bp) { ai[bp] = bI; af[bp] = bF; ag[bp] = bG; ao[bp] = bO; }

            // input contribution: Wih1 . h1(t)  (weights from smem)
            {
                const u64* hp = &s->h1buf[pair][buf][0][0];
                #pragma unroll
                for (int k = 0; k < HID; ++k) {
                    const ulonglong2 wp = *reinterpret_cast<const ulonglong2*>(&s->wih1[k][lane]);
                    const ulonglong2 hA = *reinterpret_cast<const ulonglong2*>(hp + k * BP);
                    const ulonglong2 hB = *reinterpret_cast<const ulonglong2*>(hp + k * BP + 2);
                    u64 hv[BP] = { hA.x, hA.y, hB.x, hB.y };
                    GATE_K4R(wp.x, wp.y, hv);
                }
            }
            bar_arrive64(buf ? be1 : be0);   // h1 buffer consumed

            // recurrent contribution: Whh1 . h2(t-1)  (register weights)
            {
                const u64* hp = &s->h2s[pair][0][0];
                #pragma unroll
                for (int k = 0; k < HID; ++k) {
                    const ulonglong2 hA = *reinterpret_cast<const ulonglong2*>(hp + k * BP);
                    const ulonglong2 hB = *reinterpret_cast<const ulonglong2*>(hp + k * BP + 2);
                    u64 hv[BP] = { hA.x, hA.y, hB.x, hB.y };
                    GATE_K4R(wr1[k][0], wr1[k][1], hv);
                }
            }

            // activations + h2 store
            __syncwarp();   // all lanes done reading old h2s
            #pragma unroll
            for (int bp = 0; bp < BP; ++bp) {
                float i0, i1, f0, f1, g0, g1, o0, o1;
                upk2(ai[bp], i0, i1); upk2(af[bp], f0, f1);
                upk2(ag[bp], g0, g1); upk2(ao[bp], o0, o1);
                float ca = sig_pre(f0) * c2[2*bp]   + sig_pre(i0) * tanh_ap(g0);
                float cb = sig_pre(f1) * c2[2*bp+1] + sig_pre(i1) * tanh_ap(g1);
                c2[2*bp]   = ca;  c2[2*bp+1] = cb;
                h2v[2*bp]   = sig_pre(o0) * tanh_ap(ca);
                h2v[2*bp+1] = sig_pre(o1) * tanh_ap(cb);
                s->h2s[pair][lane][bp] = pk2(h2v[2*bp], h2v[2*bp+1]);
            }
            __syncwarp();   // new h2 visible to whole warp
        }

        // ---- output head ----
        const float wo = s->wout[lane];
        #pragma unroll
        for (int b = 0; b < NB; ++b) {
            float v = h2v[b] * wo;
            #pragma unroll
            for (int off = 16; off; off >>= 1) v += __shfl_xor_sync(0xffffffffu, v, off);
            if (lane == 0) out[batch0 + b] = v + s->bout;
        }
    }
}

extern "C" void kernel_launch(void* const* d_in, const int* in_sizes, int n_in,
                              void* d_out, int out_size)
{
    (void)in_sizes; (void)n_in; (void)out_size;
    const size_t smem = sizeof(Smem);
    cudaFuncSetAttribute(lstm2_kernel, cudaFuncAttributeMaxDynamicSharedMemorySize, (int)smem);
    lstm2_kernel<<<NBLOCKS, THREADS, smem>>>(
        (const float*)d_in[0],
        (const float*)d_in[1], (const float*)d_in[2],
        (const float*)d_in[3], (const float*)d_in[4],
        (const float*)d_in[5], (const float*)d_in[6],
        (const float*)d_in[7], (const float*)d_in[8],
        (const float*)d_in[9], (const float*)d_in[10],
        (float*)d_out);
}